// round 14
// baseline (speedup 1.0000x reference)
#include <cuda_runtime.h>
#include <cuda_bf16.h>

typedef unsigned long long u64;
typedef long long ll;
typedef unsigned int u32;

// ---------------- scratch (no allocations allowed) ----------------
__device__ float g_gi_f[64 * 1024 * 384];
__device__ float g_gi_b[64 * 1024 * 384];
__device__ float g_z1[64 * 1024 * 256];
__device__ __nv_bfloat16 g_abf[2 * 64 * 1024 * 256];   // [hi | lo], lo at +16777216
__device__ __nv_bfloat16 g_whi_f[384 * 256];
__device__ __nv_bfloat16 g_wlo_f[384 * 256];
__device__ __nv_bfloat16 g_whi_b[384 * 256];
__device__ __nv_bfloat16 g_wlo_b[384 * 256];
__device__ float g_attn[64 * 1024];
__device__ float g_part[64 * 16 * 256];

static constexpr u32 BF_HALF = 16777216u;   // 64*1024*256

// ---------------- f32x2 helpers ----------------
__device__ __forceinline__ u64 ffma2(u64 a, u64 b, u64 c) {
    u64 d;
    asm("fma.rn.f32x2 %0, %1, %2, %3;" : "=l"(d) : "l"(a), "l"(b), "l"(c));
    return d;
}
__device__ __forceinline__ float2 unpack2(u64 v) {
    float2 f;
    asm("mov.b64 {%0, %1}, %2;" : "=f"(f.x), "=f"(f.y) : "l"(v));
    return f;
}
__device__ __forceinline__ float tanh_mufu(float x) {
    float y;
    asm("tanh.approx.f32 %0, %1;" : "=f"(y) : "f"(x));
    return y;
}
__device__ __forceinline__ float sig_mufu(float x) {
    return fmaf(0.5f, tanh_mufu(0.5f * x), 0.5f);
}

// ---------------- mma.sync helpers ----------------
__device__ __forceinline__ u32 smem_u32(const void* p) {
    u32 a;
    asm("{ .reg .u64 t; cvta.to.shared.u64 t, %1; cvt.u32.u64 %0, t; }"
        : "=r"(a) : "l"(p));
    return a;
}
__device__ __forceinline__ void ldsm_x4(u32* r, u32 addr) {
    asm volatile("ldmatrix.sync.aligned.m8n8.x4.shared.b16 {%0,%1,%2,%3}, [%4];"
                 : "=r"(r[0]), "=r"(r[1]), "=r"(r[2]), "=r"(r[3]) : "r"(addr));
}
__device__ __forceinline__ void ldsm_x2(u32* r, u32 addr) {
    asm volatile("ldmatrix.sync.aligned.m8n8.x2.shared.b16 {%0,%1}, [%2];"
                 : "=r"(r[0]), "=r"(r[1]) : "r"(addr));
}
__device__ __forceinline__ void mma16816(float* c, const u32* a, const u32* b) {
    asm volatile(
        "mma.sync.aligned.m16n8k16.row.col.f32.bf16.bf16.f32 "
        "{%0,%1,%2,%3}, {%4,%5,%6,%7}, {%8,%9}, {%0,%1,%2,%3};"
        : "+f"(c[0]), "+f"(c[1]), "+f"(c[2]), "+f"(c[3])
        : "r"(a[0]), "r"(a[1]), "r"(a[2]), "r"(a[3]), "r"(b[0]), "r"(b[1]));
}

// ---------------- bf16 hi/lo split conversion ----------------
__global__ void split_bf16(const float* __restrict__ a,
                           __nv_bfloat16* __restrict__ hi,
                           __nv_bfloat16* __restrict__ lo, int n4)
{
    int i = blockIdx.x * blockDim.x + threadIdx.x;
    if (i >= n4) return;
    float4 v = ((const float4*)a)[i];
    __nv_bfloat16 h0 = __float2bfloat16(v.x);
    __nv_bfloat16 h1 = __float2bfloat16(v.y);
    __nv_bfloat16 h2 = __float2bfloat16(v.z);
    __nv_bfloat16 h3 = __float2bfloat16(v.w);
    __nv_bfloat16 l0 = __float2bfloat16(v.x - __bfloat162float(h0));
    __nv_bfloat16 l1 = __float2bfloat16(v.y - __bfloat162float(h1));
    __nv_bfloat16 l2 = __float2bfloat16(v.z - __bfloat162float(h2));
    __nv_bfloat16 l3 = __float2bfloat16(v.w - __bfloat162float(h3));
    ((__nv_bfloat162*)hi)[2 * i]     = __nv_bfloat162(h0, h1);
    ((__nv_bfloat162*)hi)[2 * i + 1] = __nv_bfloat162(h2, h3);
    ((__nv_bfloat162*)lo)[2 * i]     = __nv_bfloat162(l0, l1);
    ((__nv_bfloat162*)lo)[2 * i + 1] = __nv_bfloat162(l2, l3);
}

// ---------------- tensor-core GEMM via mma.sync (R9-proven) ----------------
static constexpr int LDS = 40;

__global__ void __launch_bounds__(256, 1) mma_gemm(
    const __nv_bfloat16* __restrict__ ahi, const __nv_bfloat16* __restrict__ alo,
    const __nv_bfloat16* __restrict__ whif, const __nv_bfloat16* __restrict__ wlof,
    const __nv_bfloat16* __restrict__ whib, const __nv_bfloat16* __restrict__ wlob,
    const float* __restrict__ biasf, const float* __restrict__ biasb,
    float* __restrict__ cf, float* __restrict__ cb, int K)
{
    const int dir = blockIdx.z;
    const __nv_bfloat16* whi = dir ? whib : whif;
    const __nv_bfloat16* wlo = dir ? wlob : wlof;
    const float* bias = dir ? biasb : biasf;
    float* C = dir ? cb : cf;

    const int nBase = blockIdx.x * 128;
    const int mBase = blockIdx.y * 128;
    const int tid = threadIdx.x;
    const int lane = tid & 31;
    const int warp = tid >> 5;
    const int mw = (warp & 1) * 64;
    const int nw = (warp >> 1) * 32;

    __shared__ __nv_bfloat16 sAhi[128 * LDS];
    __shared__ __nv_bfloat16 sAlo[128 * LDS];
    __shared__ __nv_bfloat16 sWhi[128 * LDS];
    __shared__ __nv_bfloat16 sWlo[128 * LDS];

    float acc[4][4][4];
#pragma unroll
    for (int i = 0; i < 4; i++)
#pragma unroll
        for (int j = 0; j < 4; j++)
#pragma unroll
            for (int r = 0; r < 4; r++) acc[i][j][r] = 0.0f;

    const u32 bAhi = smem_u32(sAhi), bAlo = smem_u32(sAlo);
    const u32 bWhi = smem_u32(sWhi), bWlo = smem_u32(sWlo);

    const u32 a_row = mw + (lane & 15);
    const u32 a_col = (lane >> 4) * 8;
    const u32 b_row = nw + (lane & 7);
    const u32 b_col = ((lane >> 3) & 1) * 8;

    const int nChunks = K >> 5;
    for (int c = 0; c < nChunks; c++) {
        const int kc = c << 5;
        __syncthreads();
#pragma unroll
        for (int it = 0; it < 4; it++) {
            int u = it * 256 + tid;
            int row = u >> 3, seg = u & 7;
            u32 so = (u32)(row * LDS + seg * 4);
            ll asrc = (ll)(mBase + row) * K + kc + seg * 4;
            ll wsrc = (ll)(nBase + row) * K + kc + seg * 4;
            *(u64*)(sAhi + so) = *(const u64*)(ahi + asrc);
            *(u64*)(sAlo + so) = *(const u64*)(alo + asrc);
            *(u64*)(sWhi + so) = *(const u64*)(whi + wsrc);
            *(u64*)(sWlo + so) = *(const u64*)(wlo + wsrc);
        }
        __syncthreads();

#pragma unroll
        for (int ks = 0; ks < 2; ks++) {
            const u32 k16 = ks * 16;
            u32 fahi[4][4], falo[4][4];
#pragma unroll
            for (int ms = 0; ms < 4; ms++) {
                u32 off = ((a_row + ms * 16) * LDS + a_col + k16) * 2;
                ldsm_x4(fahi[ms], bAhi + off);
                ldsm_x4(falo[ms], bAlo + off);
            }
            u32 fbhi[4][2], fblo[4][2];
#pragma unroll
            for (int ns = 0; ns < 4; ns++) {
                u32 off = ((b_row + ns * 8) * LDS + b_col + k16) * 2;
                ldsm_x2(fbhi[ns], bWhi + off);
                ldsm_x2(fblo[ns], bWlo + off);
            }
#pragma unroll
            for (int ms = 0; ms < 4; ms++)
#pragma unroll
                for (int ns = 0; ns < 4; ns++) {
                    mma16816(acc[ms][ns], fahi[ms], fbhi[ns]);
                    mma16816(acc[ms][ns], fahi[ms], fblo[ns]);
                    mma16816(acc[ms][ns], falo[ms], fbhi[ns]);
                }
        }
    }

    const int cbase = nBase + nw + 2 * (lane & 3);
    float2 bv[4];
#pragma unroll
    for (int ns = 0; ns < 4; ns++) {
        bv[ns].x = __ldg(&bias[cbase + ns * 8]);
        bv[ns].y = __ldg(&bias[cbase + ns * 8 + 1]);
    }
#pragma unroll
    for (int ms = 0; ms < 4; ms++) {
        int r0 = mBase + mw + ms * 16 + (lane >> 2);
#pragma unroll
        for (int ns = 0; ns < 4; ns++) {
            int col = cbase + ns * 8;
            float2 lo2, hi2;
            lo2.x = acc[ms][ns][0] + bv[ns].x;
            lo2.y = acc[ms][ns][1] + bv[ns].y;
            hi2.x = acc[ms][ns][2] + bv[ns].x;
            hi2.y = acc[ms][ns][3] + bv[ns].y;
            *(float2*)(C + (ll)r0 * 384 + col)       = lo2;
            *(float2*)(C + (ll)(r0 + 8) * 384 + col) = hi2;
        }
    }
}

// ---------------- GRU scan: quad-per-row, templated output, reg-diet --------
template <int WBF>
__global__ void __launch_bounds__(512, 1) gru_scan_t(
    const float* __restrict__ gif, const float* __restrict__ gib,
    const float* __restrict__ whf, const float* __restrict__ bhf,
    const float* __restrict__ whb, const float* __restrict__ bhb,
    float* __restrict__ outf, __nv_bfloat16* __restrict__ obf)
{
    const int b   = blockIdx.x & 63;
    const int dir = blockIdx.x >> 6;
    const float* gi  = dir ? gib : gif;
    const float* whh = dir ? whb : whf;
    const float* bhh = dir ? bhb : bhf;

    const int tid = threadIdx.x;
    const int i = tid >> 2;
    const int g = tid & 3;
    const int laneBase = (tid & 31) & ~3;

    u64 wr[16], wz[16], wn[16];
    {
        const u64* pr = (const u64*)(whh + (i      ) * 128 + g * 32);
        const u64* pz = (const u64*)(whh + (i + 128) * 128 + g * 32);
        const u64* pn = (const u64*)(whh + (i + 256) * 128 + g * 32);
#pragma unroll
        for (int k = 0; k < 16; k++) { wr[k] = pr[k]; wz[k] = pz[k]; wn[k] = pn[k]; }
    }
    const float br = bhh[i], bz = bhh[i + 128], bn = bhh[i + 256];

    __shared__ __align__(16) float hsm[2][144];
    if (tid < 144) hsm[0][tid] = 0.0f;
    __syncthreads();

    const int step = dir ? -1 : 1;
    int tt = dir ? 1023 : 0;
    const int grow = i + 128 * ((g == 3) ? 0 : g);
    const float* gip = gi + (ll)b * (1024 * 384) + grow;
    float* outp = outf + (ll)b * (1024 * 256) + dir * 128 + i;
    __nv_bfloat16* obp = obf + (ll)b * (1024 * 256) + dir * 128 + i;
    const int hsl = ((i >> 5) * 36) + (i & 31);

    float gpre[4];
#pragma unroll
    for (int d = 0; d < 4; d++)
        gpre[d] = gip[((tt + d * step) & 1023) * 384];

    float hprev = 0.0f;
    int buf = 0;

    for (int t = 0; t < 1024; t += 4) {
#pragma unroll
        for (int u = 0; u < 4; u++) {
            float gcur = gpre[u];
            gpre[u] = gip[((tt + 4 * step) & 1023) * 384];

            const ulonglong2* hp2 = (const ulonglong2*)(&hsm[buf][g * 36]);
            u64 ar = 0ULL, az = 0ULL, an = 0ULL;
#pragma unroll
            for (int q = 0; q < 8; q++) {
                ulonglong2 hv = hp2[q];
                ar = ffma2(wr[2 * q], hv.x, ar);
                ar = ffma2(wr[2 * q + 1], hv.y, ar);
                az = ffma2(wz[2 * q], hv.x, az);
                az = ffma2(wz[2 * q + 1], hv.y, az);
                an = ffma2(wn[2 * q], hv.x, an);
                an = ffma2(wn[2 * q + 1], hv.y, an);
            }
            float2 fr = unpack2(ar), fz = unpack2(az), fn = unpack2(an);
            float sr = fr.x + fr.y, sz = fz.x + fz.y, sn = fn.x + fn.y;
            sr += __shfl_xor_sync(0xffffffffu, sr, 1);
            sr += __shfl_xor_sync(0xffffffffu, sr, 2);
            sz += __shfl_xor_sync(0xffffffffu, sz, 1);
            sz += __shfl_xor_sync(0xffffffffu, sz, 2);
            sn += __shfl_xor_sync(0xffffffffu, sn, 1);
            sn += __shfl_xor_sync(0xffffffffu, sn, 2);
            float gr = __shfl_sync(0xffffffffu, gcur, laneBase + 0);
            float gz = __shfl_sync(0xffffffffu, gcur, laneBase + 1);
            float gn = __shfl_sync(0xffffffffu, gcur, laneBase + 2);
            float r  = sig_mufu(gr + sr + br);
            float zv = sig_mufu(gz + sz + bz);
            float n  = tanh_mufu(fmaf(r, sn + bn, gn));
            float hnew = fmaf(zv, hprev - n, n);
            hprev = hnew;
            if (g == 0) {
                hsm[buf ^ 1][hsl] = hnew;
                u32 off = (u32)tt * 256u;
                if (WBF) {
                    __nv_bfloat16 h16 = __float2bfloat16(hnew);
                    obp[off] = h16;
                    obp[BF_HALF + off] = __float2bfloat16(hnew - __bfloat162float(h16));
                } else {
                    outp[off] = hnew;
                }
            }
            __syncthreads();
            buf ^= 1;
            tt += step;
        }
    }
}

// ---------------- pooling, parallelized (R13-proven) ----------------
__global__ __launch_bounds__(256) void scores_k(
    const float* __restrict__ z1, const float* __restrict__ attn_w,
    const float* __restrict__ attn_b, float* __restrict__ sc)
{
    const int b = blockIdx.y;
    const int t = blockIdx.x * 8 + (threadIdx.x >> 5);
    const int lane = threadIdx.x & 31;
    const float* zr = z1 + ((ll)b * 1024 + t) * 256 + lane * 8;
    const float* ap = attn_w + lane * 8;
    float4 v0 = *(const float4*)zr;
    float4 v1 = *(const float4*)(zr + 4);
    float4 w0 = __ldg((const float4*)ap);
    float4 w1 = __ldg((const float4*)(ap + 4));
    float p = v0.x * w0.x;
    p = fmaf(v0.y, w0.y, p); p = fmaf(v0.z, w0.z, p); p = fmaf(v0.w, w0.w, p);
    p = fmaf(v1.x, w1.x, p); p = fmaf(v1.y, w1.y, p);
    p = fmaf(v1.z, w1.z, p); p = fmaf(v1.w, w1.w, p);
#pragma unroll
    for (int o = 16; o; o >>= 1) p += __shfl_down_sync(0xffffffffu, p, o);
    if (lane == 0) sc[b * 1024 + t] = p + __ldg(&attn_b[0]);
}

__global__ __launch_bounds__(256) void softmax_k(
    const float* __restrict__ sc, float* __restrict__ a)
{
    const int b = blockIdx.x;
    const int tid = threadIdx.x;
    const int lane = tid & 31;
    const int wrp = tid >> 5;
    __shared__ float red[34];

    float4 v = ((const float4*)(sc + b * 1024))[tid];
    float mx = fmaxf(fmaxf(v.x, v.y), fmaxf(v.z, v.w));
#pragma unroll
    for (int o = 16; o; o >>= 1) mx = fmaxf(mx, __shfl_xor_sync(0xffffffffu, mx, o));
    if (lane == 0) red[wrp] = mx;
    __syncthreads();
    if (tid == 0) {
        float m = red[0];
        for (int i = 1; i < 8; i++) m = fmaxf(m, red[i]);
        red[32] = m;
    }
    __syncthreads();
    mx = red[32];
    float e0 = __expf(v.x - mx), e1 = __expf(v.y - mx);
    float e2 = __expf(v.z - mx), e3 = __expf(v.w - mx);
    float s = (e0 + e1) + (e2 + e3);
#pragma unroll
    for (int o = 16; o; o >>= 1) s += __shfl_xor_sync(0xffffffffu, s, o);
    if (lane == 0) red[wrp] = s;
    __syncthreads();
    if (tid == 0) {
        float m = 0.0f;
        for (int i = 0; i < 8; i++) m += red[i];
        red[33] = __fdividef(1.0f, m);
    }
    __syncthreads();
    const float inv = red[33];
    float4 o4 = make_float4(e0 * inv, e1 * inv, e2 * inv, e3 * inv);
    ((float4*)(a + b * 1024))[tid] = o4;
}

__global__ __launch_bounds__(256) void part_k(
    const float* __restrict__ z1, const float* __restrict__ a,
    float* __restrict__ part)
{
    const int chunk = blockIdx.x;   // 0..15
    const int b = blockIdx.y;
    const int tid = threadIdx.x;
    __shared__ float asm_[64];
    if (tid < 64) asm_[tid] = a[b * 1024 + chunk * 64 + tid];
    __syncthreads();
    const float* zb = z1 + ((ll)b * 1024 + chunk * 64) * 256 + tid;
    float a0 = 0.0f, a1 = 0.0f, a2 = 0.0f, a3 = 0.0f;
#pragma unroll
    for (int t = 0; t < 64; t += 4) {
        a0 = fmaf(asm_[t + 0], zb[(t + 0) * 256], a0);
        a1 = fmaf(asm_[t + 1], zb[(t + 1) * 256], a1);
        a2 = fmaf(asm_[t + 2], zb[(t + 2) * 256], a2);
        a3 = fmaf(asm_[t + 3], zb[(t + 3) * 256], a3);
    }
    part[(b * 16 + chunk) * 256 + tid] = (a0 + a1) + (a2 + a3);
}

__global__ __launch_bounds__(256) void heads_k(
    const float* __restrict__ part,
    const float* __restrict__ motor_w, const float* __restrict__ motor_b,
    const float* __restrict__ state_w, const float* __restrict__ state_b,
    const int* __restrict__ motor_k, float* __restrict__ out)
{
    const int b = blockIdx.x;
    const int tid = threadIdx.x;
    const int lane = tid & 31;
    const int wrp = tid >> 5;
    __shared__ float pl[256];

    float s = 0.0f;
#pragma unroll
    for (int c = 0; c < 16; c++)
        s += part[(b * 16 + c) * 256 + tid];
    pl[tid] = s;
    __syncthreads();

    if (wrp < 7) {
        const float* wv;
        float bias2;
        int k = motor_k[b];
        if (wrp < 5) {
            wv = motor_w + wrp * 256;
            bias2 = motor_b[wrp];
        } else {
            int c = wrp - 5;
            wv = state_w + (k * 2 + c) * 256;
            bias2 = state_b[k * 2 + c];
        }
        float p = 0.0f;
#pragma unroll
        for (int q = 0; q < 8; q++)
            p = fmaf(pl[lane + 32 * q], wv[lane + 32 * q], p);
#pragma unroll
        for (int o = 16; o; o >>= 1) p += __shfl_down_sync(0xffffffffu, p, o);
        if (lane == 0) {
            if (wrp < 5) out[b * 5 + wrp] = p + bias2;
            else         out[320 + b * 2 + (wrp - 5)] = p + bias2;
        }
    }
}

// ---------------- launcher ----------------
extern "C" void kernel_launch(void* const* d_in, const int* in_sizes, int n_in,
                              void* d_out, int out_size)
{
    const float* x        = (const float*)d_in[0];
    const int*   motor_k  = (const int*)d_in[1];
    const float* wih_l0f  = (const float*)d_in[2];
    const float* whh_l0f  = (const float*)d_in[3];
    const float* bih_l0f  = (const float*)d_in[4];
    const float* bhh_l0f  = (const float*)d_in[5];
    const float* wih_l0b  = (const float*)d_in[6];
    const float* whh_l0b  = (const float*)d_in[7];
    const float* bih_l0b  = (const float*)d_in[8];
    const float* bhh_l0b  = (const float*)d_in[9];
    const float* wih_l1f  = (const float*)d_in[10];
    const float* whh_l1f  = (const float*)d_in[11];
    const float* bih_l1f  = (const float*)d_in[12];
    const float* bhh_l1f  = (const float*)d_in[13];
    const float* wih_l1b  = (const float*)d_in[14];
    const float* whh_l1b  = (const float*)d_in[15];
    const float* bih_l1b  = (const float*)d_in[16];
    const float* bhh_l1b  = (const float*)d_in[17];
    const float* attn_w   = (const float*)d_in[18];
    const float* attn_b   = (const float*)d_in[19];
    const float* motor_w  = (const float*)d_in[20];
    const float* motor_b  = (const float*)d_in[21];
    const float* state_w  = (const float*)d_in[22];
    const float* state_b  = (const float*)d_in[23];

    float *gif, *gib, *z1, *attn, *partp;
    __nv_bfloat16 *abf, *whiF, *wloF, *whiB, *wloB;
    cudaGetSymbolAddress((void**)&gif, g_gi_f);
    cudaGetSymbolAddress((void**)&gib, g_gi_b);
    cudaGetSymbolAddress((void**)&z1, g_z1);
    cudaGetSymbolAddress((void**)&attn, g_attn);
    cudaGetSymbolAddress((void**)&partp, g_part);
    cudaGetSymbolAddress((void**)&abf, g_abf);
    cudaGetSymbolAddress((void**)&whiF, g_whi_f);
    cudaGetSymbolAddress((void**)&wloF, g_wlo_f);
    cudaGetSymbolAddress((void**)&whiB, g_whi_b);
    cudaGetSymbolAddress((void**)&wloB, g_wlo_b);

    __nv_bfloat16* ahi = abf;
    __nv_bfloat16* alo = abf + BF_HALF;

    dim3 gg(3, 512, 2);

    // ---- layer 0 (K=64): x -> bf16, gemm, scan (emits bf16 hi/lo) ----
    split_bf16<<<4096, 256>>>(x, ahi, alo, 65536 * 64 / 4);
    split_bf16<<<24, 256>>>(wih_l0f, whiF, wloF, 384 * 64 / 4);
    split_bf16<<<24, 256>>>(wih_l0b, whiB, wloB, 384 * 64 / 4);
    mma_gemm<<<gg, 256>>>(ahi, alo, whiF, wloF, whiB, wloB,
                          bih_l0f, bih_l0b, gif, gib, 64);
    gru_scan_t<1><<<128, 512>>>(gif, gib, whh_l0f, bhh_l0f, whh_l0b, bhh_l0b,
                                (float*)0, abf);

    // ---- layer 1 (K=256): gemm on scan's bf16 output, scan -> float z1 ----
    split_bf16<<<96, 256>>>(wih_l1f, whiF, wloF, 384 * 256 / 4);
    split_bf16<<<96, 256>>>(wih_l1b, whiB, wloB, 384 * 256 / 4);
    mma_gemm<<<gg, 256>>>(ahi, alo, whiF, wloF, whiB, wloB,
                          bih_l1f, bih_l1b, gif, gib, 256);
    gru_scan_t<0><<<128, 512>>>(gif, gib, whh_l1f, bhh_l1f, whh_l1b, bhh_l1b,
                                z1, (__nv_bfloat16*)0);

    // ---- pooling + heads ----
    scores_k<<<dim3(128, 64), 256>>>(z1, attn_w, attn_b, attn);
    softmax_k<<<64, 256>>>(attn, attn);
    part_k<<<dim3(16, 64), 256>>>(z1, attn, partp);
    heads_k<<<64, 256>>>(partp, motor_w, motor_b, state_w, state_b,
                         motor_k, (float*)d_out);
}